// round 13
// baseline (speedup 1.0000x reference)
#include <cuda_runtime.h>
#include <math.h>

// Problem constants
#define VD    256
#define VD4   64
#define LL    32
#define MM    4096
#define CC    4096
#define ROWS  (MM + 1)     // mems_enc rows (mems + xs)
#define EPS   1e-8f
#define NLHS  256          // blocks for att @ mems_enc partial stage

// ys + cands encode tasks: 4097 seqs -> 1025 groups of 4
#define ENC_TASKS   1025
#define COS_TASKS   1025   // cos: ceil(4097/4)
#define TILE_TASKS  1025   // tile: ceil(4097/4)
#define COS_ENC     300
#define LHSP_ENC    300
#define LHSF_ENC    300
#define TILE_ENC    125    // 300+300+300+125 = 1025

// Scratch (allocation-free: __device__ globals)
__device__ float g_mems_enc[ROWS * VD];
__device__ float g_cos[ROWS];
__device__ float g_partial[NLHS * VD];
__device__ float g_lhs[VD];

// ---------------------------------------------------------------------------
// One ys/cands encode task (4 seqs per block). Whole block executes this.
// task e covers s2 = 4e .. 4e+3; s2==0 -> ys, else cand (s2-1).
// ---------------------------------------------------------------------------
__device__ __forceinline__ void encode_task(int task, int g, int j,
                                            int (*toks)[LL], float (*ws)[LL],
                                            const int* __restrict__ ys,
                                            const int* __restrict__ cands,
                                            const float* __restrict__ lt,
                                            const float* __restrict__ freqs,
                                            float* __restrict__ out_ys)
{
    const int s2 = task * 4 + g;
    const bool active = (s2 < MM + 1);     // 4097 seqs
    const int* src = cands;
    float4* dst = nullptr;
    if (active) {
        if (s2 == 0) { src = ys; dst = reinterpret_cast<float4*>(out_ys); }
        else {
            const int c = s2 - 1;
            src = cands + (size_t)c * LL;
            dst = reinterpret_cast<float4*>(out_ys) + (size_t)(1 + c) * VD4;
        }
    }
    if (active && j < LL) {
        int tok = src[j];
        toks[g][j] = tok;
        float w = freqs[tok];
        float sq = w * w;
        #pragma unroll
        for (int o = 16; o; o >>= 1) sq += __shfl_xor_sync(0xFFFFFFFFu, sq, o);
        ws[g][j] = w * rsqrtf(sq);
    }
    __syncthreads();
    if (active) {
        const float4* __restrict__ lt4 = reinterpret_cast<const float4*>(lt);
        float4 acc = make_float4(0.f, 0.f, 0.f, 0.f);
        #pragma unroll
        for (int l = 0; l < LL; l++) {
            const float w = ws[g][l];
            const float4 e = lt4[(size_t)toks[g][l] * VD4 + j];
            acc.x = fmaf(w, e.x, acc.x);
            acc.y = fmaf(w, e.y, acc.y);
            acc.z = fmaf(w, e.z, acc.z);
            acc.w = fmaf(w, e.w, acc.w);
        }
        __stcs(dst + j, acc);              // final output, never re-read
    }
}

// ---------------------------------------------------------------------------
// Kernel 1: encode mems + xs only (4097 seqs, 1025 blocks x 256).
// ---------------------------------------------------------------------------
__global__ void encode_mems_kernel(const int* __restrict__ xs,
                                   const int* __restrict__ mems,
                                   const float* __restrict__ lt,
                                   const float* __restrict__ freqs)
{
    __shared__ int   toks[4][LL];
    __shared__ float ws[4][LL];

    const int t = threadIdx.x;
    const int g = t >> 6;
    const int j = t & 63;
    const int s = blockIdx.x * 4 + g;
    const bool active = (s < MM + 1);

    const int* src = mems;
    float4* dst = nullptr;
    if (active) {
        if (s < MM) {
            src = mems + (size_t)s * LL;
            dst = reinterpret_cast<float4*>(g_mems_enc) + (size_t)s * VD4;
        } else {
            src = xs;
            dst = reinterpret_cast<float4*>(g_mems_enc) + (size_t)MM * VD4;
        }
    }
    if (active && j < LL) {
        int tok = src[j];
        toks[g][j] = tok;
        float w = freqs[tok];
        float sq = w * w;
        #pragma unroll
        for (int o = 16; o; o >>= 1) sq += __shfl_xor_sync(0xFFFFFFFFu, sq, o);
        ws[g][j] = w * rsqrtf(sq);
    }
    __syncthreads();
    if (active) {
        const float4* __restrict__ lt4 = reinterpret_cast<const float4*>(lt);
        float4 acc = make_float4(0.f, 0.f, 0.f, 0.f);
        #pragma unroll
        for (int l = 0; l < LL; l++) {
            const float w = ws[g][l];
            const float4 e = lt4[(size_t)toks[g][l] * VD4 + j];
            acc.x = fmaf(w, e.x, acc.x);
            acc.y = fmaf(w, e.y, acc.y);
            acc.z = fmaf(w, e.z, acc.z);
            acc.w = fmaf(w, e.w, acc.w);
        }
        __stcs(dst + j, acc);              // streaming: keep lt L2-resident
    }
}

// ---------------------------------------------------------------------------
// Kernel 2: cos (blocks 0..1024) + stuffed enc tasks 0..299.
// ---------------------------------------------------------------------------
__global__ void cos_kernel(const int* __restrict__ ys,
                           const int* __restrict__ cands,
                           const float* __restrict__ lt,
                           const float* __restrict__ freqs,
                           float* __restrict__ out_ys)
{
    __shared__ int   toks[4][LL];
    __shared__ float ws[4][LL];
    __shared__ float red[4][2][3];

    const int t = threadIdx.x;
    const int g = t >> 6;
    const int j = t & 63;

    if (blockIdx.x >= COS_TASKS) {
        encode_task(blockIdx.x - COS_TASKS, g, j, toks, ws, ys, cands, lt, freqs, out_ys);
        return;
    }

    const int r = blockIdx.x * 4 + g;
    if (r >= ROWS) return;

    const float4* __restrict__ enc4 = reinterpret_cast<const float4*>(g_mems_enc);
    const float4 mv = __ldcs(enc4 + (size_t)r * VD4 + j);
    const float4 xv = enc4[(size_t)MM * VD4 + j];

    float dot = mv.x * xv.x + mv.y * xv.y + mv.z * xv.z + mv.w * xv.w;
    float mn  = mv.x * mv.x + mv.y * mv.y + mv.z * mv.z + mv.w * mv.w;
    float xn  = xv.x * xv.x + xv.y * xv.y + xv.z * xv.z + xv.w * xv.w;

    #pragma unroll
    for (int o = 16; o; o >>= 1) {
        dot += __shfl_xor_sync(0xFFFFFFFFu, dot, o);
        mn  += __shfl_xor_sync(0xFFFFFFFFu, mn, o);
        xn  += __shfl_xor_sync(0xFFFFFFFFu, xn, o);
    }
    const int wig = j >> 5;
    if ((j & 31) == 0) {
        red[g][wig][0] = dot; red[g][wig][1] = mn; red[g][wig][2] = xn;
    }
    __syncthreads();

    if (j == 0) {
        float d  = red[g][0][0] + red[g][1][0];
        float m2 = red[g][0][1] + red[g][1][1];
        float x2 = red[g][0][2] + red[g][1][2];
        float an = fmaxf(sqrtf(x2), EPS);
        float bn = fmaxf(sqrtf(m2), EPS);
        g_cos[r] = d / (an * bn);
    }
}

// ---------------------------------------------------------------------------
// Kernel 3: lhs_partial (blocks 0..255) + stuffed enc tasks 300..599.
// Per-block softmax recompute from g_cos (L2-hot), then 16-row partial.
// ---------------------------------------------------------------------------
__global__ void lhs_partial_kernel(const int* __restrict__ ys,
                                   const int* __restrict__ cands,
                                   const float* __restrict__ lt,
                                   const float* __restrict__ freqs,
                                   float* __restrict__ out_ys)
{
    __shared__ int    toks[4][LL];
    __shared__ float  ws[4][LL];
    __shared__ float  sred[8];
    __shared__ float4 scomb[4][VD4];

    const int t = threadIdx.x;
    const int g = t >> 6;
    const int j = t & 63;
    const int lane = t & 31;
    const int wid  = t >> 5;

    if (blockIdx.x >= NLHS) {
        encode_task(LHSP_ENC * 0 + 300 + (blockIdx.x - NLHS), g, j, toks, ws,
                    ys, cands, lt, freqs, out_ys);
        return;
    }

    // --- softmax stats over g_cos ---
    float m = -INFINITY;
    for (int r = t; r < ROWS; r += 256) m = fmaxf(m, g_cos[r]);
    #pragma unroll
    for (int o = 16; o; o >>= 1) m = fmaxf(m, __shfl_xor_sync(0xFFFFFFFFu, m, o));
    if (lane == 0) sred[wid] = m;
    __syncthreads();
    {
        float mm = (t < 8) ? sred[t] : -INFINITY;
        if (wid == 0) {
            #pragma unroll
            for (int o = 4; o; o >>= 1) mm = fmaxf(mm, __shfl_xor_sync(0xFFFFFFFFu, mm, o));
            if (lane == 0) sred[0] = mm;
        }
    }
    __syncthreads();
    m = sred[0];
    __syncthreads();

    float s = 0.0f;
    for (int r = t; r < ROWS; r += 256) s += __expf(g_cos[r] - m);
    #pragma unroll
    for (int o = 16; o; o >>= 1) s += __shfl_xor_sync(0xFFFFFFFFu, s, o);
    if (lane == 0) sred[wid] = s;
    __syncthreads();
    {
        float ss = (t < 8) ? sred[t] : 0.0f;
        if (wid == 0) {
            #pragma unroll
            for (int o = 4; o; o >>= 1) ss += __shfl_xor_sync(0xFFFFFFFFu, ss, o);
            if (lane == 0) sred[0] = ss;
        }
    }
    __syncthreads();
    const float inv = 1.0f / sred[0];

    // --- partial weighted sum: 16 contiguous rows per block (4 per group) ---
    const int base = (blockIdx.x * 4 + g) * 4;
    const float4* __restrict__ enc4 = reinterpret_cast<const float4*>(g_mems_enc);
    float4 acc = make_float4(0.f, 0.f, 0.f, 0.f);

    #pragma unroll
    for (int k = 0; k < 4; k++) {
        const int r = base + k;
        const float a = __expf(g_cos[r] - m) * inv;
        const float4 e = __ldcs(enc4 + (size_t)r * VD4 + j);
        acc.x = fmaf(a, e.x, acc.x);
        acc.y = fmaf(a, e.y, acc.y);
        acc.z = fmaf(a, e.z, acc.z);
        acc.w = fmaf(a, e.w, acc.w);
    }
    if (blockIdx.x == 0 && g == 0) {       // fold row 4096 (xs)
        const float a = __expf(g_cos[MM] - m) * inv;
        const float4 e = enc4[(size_t)MM * VD4 + j];
        acc.x = fmaf(a, e.x, acc.x);
        acc.y = fmaf(a, e.y, acc.y);
        acc.z = fmaf(a, e.z, acc.z);
        acc.w = fmaf(a, e.w, acc.w);
    }

    scomb[g][j] = acc;
    __syncthreads();

    if (g == 0) {
        float4 a0 = scomb[0][j], a1 = scomb[1][j], a2 = scomb[2][j], a3 = scomb[3][j];
        float4 r;
        r.x = (a0.x + a1.x) + (a2.x + a3.x);
        r.y = (a0.y + a1.y) + (a2.y + a3.y);
        r.z = (a0.z + a1.z) + (a2.z + a3.z);
        r.w = (a0.w + a1.w) + (a2.w + a3.w);
        reinterpret_cast<float4*>(g_partial)[(size_t)blockIdx.x * VD4 + j] = r;
    }
}

// ---------------------------------------------------------------------------
// Kernel 4: lhs_final (blocks 0..63, one per float4 column) + enc 600..899.
// ---------------------------------------------------------------------------
__global__ void lhs_final_kernel(const int* __restrict__ ys,
                                 const int* __restrict__ cands,
                                 const float* __restrict__ lt,
                                 const float* __restrict__ freqs,
                                 float* __restrict__ out_ys)
{
    __shared__ int    toks[4][LL];
    __shared__ float  ws[4][LL];
    __shared__ float4 sred4[8];

    const int t = threadIdx.x;
    const int g = t >> 6;
    const int jj = t & 63;

    if (blockIdx.x >= VD4) {
        encode_task(600 + (blockIdx.x - VD4), g, jj, toks, ws, ys, cands, lt, freqs, out_ys);
        return;
    }

    const int col = blockIdx.x;
    const int lane = t & 31;
    const int wid  = t >> 5;

    const float4* __restrict__ p4 = reinterpret_cast<const float4*>(g_partial);
    float4 v = p4[(size_t)t * VD4 + col];

    #pragma unroll
    for (int o = 16; o; o >>= 1) {
        v.x += __shfl_xor_sync(0xFFFFFFFFu, v.x, o);
        v.y += __shfl_xor_sync(0xFFFFFFFFu, v.y, o);
        v.z += __shfl_xor_sync(0xFFFFFFFFu, v.z, o);
        v.w += __shfl_xor_sync(0xFFFFFFFFu, v.w, o);
    }
    if (lane == 0) sred4[wid] = v;
    __syncthreads();

    if (t < 32) {
        float4 r = (lane < 8) ? sred4[lane] : make_float4(0.f, 0.f, 0.f, 0.f);
        #pragma unroll
        for (int o = 4; o; o >>= 1) {
            r.x += __shfl_xor_sync(0xFFFFFFFFu, r.x, o);
            r.y += __shfl_xor_sync(0xFFFFFFFFu, r.y, o);
            r.z += __shfl_xor_sync(0xFFFFFFFFu, r.z, o);
            r.w += __shfl_xor_sync(0xFFFFFFFFu, r.w, o);
        }
        if (lane == 0) reinterpret_cast<float4*>(g_lhs)[col] = r;
    }
}

// ---------------------------------------------------------------------------
// Kernel 5: tile (blocks 0..1024, 4 rows each) + stuffed enc tasks 900..1024.
// ---------------------------------------------------------------------------
__global__ void tile_kernel(float* __restrict__ out_xs,
                            const int* __restrict__ ys,
                            const int* __restrict__ cands,
                            const float* __restrict__ lt,
                            const float* __restrict__ freqs,
                            float* __restrict__ out_ys)
{
    __shared__ int   toks[4][LL];
    __shared__ float ws[4][LL];

    const int t = threadIdx.x;
    const int g = t >> 6;
    const int j = t & 63;

    if (blockIdx.x >= TILE_TASKS) {
        encode_task(900 + (blockIdx.x - TILE_TASKS), g, j, toks, ws, ys, cands, lt, freqs, out_ys);
        return;
    }

    const int row = blockIdx.x * 4 + g;
    if (row <= CC) {
        const float4 v = reinterpret_cast<const float4*>(g_lhs)[j];
        __stcs(reinterpret_cast<float4*>(out_xs) + (size_t)row * VD4 + j, v);
    }
}

// ---------------------------------------------------------------------------
extern "C" void kernel_launch(void* const* d_in, const int* in_sizes, int n_in,
                              void* d_out, int out_size)
{
    const int*   xs    = (const int*)  d_in[0];
    const int*   mems  = (const int*)  d_in[1];
    const int*   ys    = (const int*)  d_in[2];
    const int*   cands = (const int*)  d_in[3];
    const float* lt    = (const float*)d_in[4];
    const float* freqs = (const float*)d_in[5];

    float* out    = (float*)d_out;
    float* out_xs = out;                          // [C+1, D]
    float* out_ys = out + (size_t)(CC + 1) * VD;  // [C+1, D]

    encode_mems_kernel<<<1025, VD>>>(xs, mems, lt, freqs);
    cos_kernel<<<COS_TASKS + COS_ENC, VD>>>(ys, cands, lt, freqs, out_ys);
    lhs_partial_kernel<<<NLHS + LHSP_ENC, VD>>>(ys, cands, lt, freqs, out_ys);
    lhs_final_kernel<<<VD4 + LHSF_ENC, VD>>>(ys, cands, lt, freqs, out_ys);
    tile_kernel<<<TILE_TASKS + TILE_ENC, VD>>>(out_xs, ys, cands, lt, freqs, out_ys);
}

// round 16
// speedup vs baseline: 1.5004x; 1.5004x over previous
#include <cuda_runtime.h>
#include <math.h>

// Problem constants
#define VD    256
#define VD4   64
#define LL    32
#define MM    4096
#define CC    4096
#define ROWS  (MM + 1)     // mems_enc rows (mems + xs)
#define EPS   1e-8f
#define NLHS  256          // blocks for att @ mems_enc partial stage

// Scratch (allocation-free: __device__ globals)
__device__ float g_mems_enc[ROWS * VD];
__device__ float g_cos[ROWS];
__device__ float g_partial[NLHS * VD];
__device__ float g_lhs[VD];

// ---------------------------------------------------------------------------
// Kernel 1a: encode mems + xs (4097 seqs, 1025 blocks x 256).
// Each 64-thread group = 1 sequence; thread j owns one float4 column.
// Streaming stores: protect lt's L2 residency (R8-measured best).
// ---------------------------------------------------------------------------
__global__ void encode_mems_kernel(const int* __restrict__ xs,
                                   const int* __restrict__ mems,
                                   const float* __restrict__ lt,
                                   const float* __restrict__ freqs)
{
    __shared__ int   toks[4][LL];
    __shared__ float ws[4][LL];

    const int t = threadIdx.x;
    const int g = t >> 6;
    const int j = t & 63;
    const int s = blockIdx.x * 4 + g;
    const bool active = (s < MM + 1);

    const int* src = mems;
    float4* dst = nullptr;
    if (active) {
        if (s < MM) {
            src = mems + (size_t)s * LL;
            dst = reinterpret_cast<float4*>(g_mems_enc) + (size_t)s * VD4;
        } else {
            src = xs;
            dst = reinterpret_cast<float4*>(g_mems_enc) + (size_t)MM * VD4;
        }
    }
    if (active && j < LL) {
        int tok = src[j];
        toks[g][j] = tok;
        float w = freqs[tok];
        float sq = w * w;
        #pragma unroll
        for (int o = 16; o; o >>= 1) sq += __shfl_xor_sync(0xFFFFFFFFu, sq, o);
        ws[g][j] = w * rsqrtf(sq);
    }
    __syncthreads();
    if (active) {
        const float4* __restrict__ lt4 = reinterpret_cast<const float4*>(lt);
        float4 acc = make_float4(0.f, 0.f, 0.f, 0.f);
        #pragma unroll
        for (int l = 0; l < LL; l++) {
            const float w = ws[g][l];
            const float4 e = lt4[(size_t)toks[g][l] * VD4 + j];
            acc.x = fmaf(w, e.x, acc.x);
            acc.y = fmaf(w, e.y, acc.y);
            acc.z = fmaf(w, e.z, acc.z);
            acc.w = fmaf(w, e.w, acc.w);
        }
        __stcs(dst + j, acc);
    }
}

// ---------------------------------------------------------------------------
// Kernel 1b: encode ys + cands (4097 seqs, 1025 blocks x 256) -> out_ys.
// Independent of everything else; runs as a parallel graph branch.
// ---------------------------------------------------------------------------
__global__ void encode_out_kernel(const int* __restrict__ ys,
                                  const int* __restrict__ cands,
                                  const float* __restrict__ lt,
                                  const float* __restrict__ freqs,
                                  float* __restrict__ out_ys)
{
    __shared__ int   toks[4][LL];
    __shared__ float ws[4][LL];

    const int t = threadIdx.x;
    const int g = t >> 6;
    const int j = t & 63;
    const int s = blockIdx.x * 4 + g;
    const bool active = (s < MM + 1);      // 4097 seqs: ys + 4096 cands

    const int* src = cands;
    float4* dst = nullptr;
    if (active) {
        if (s == 0) { src = ys; dst = reinterpret_cast<float4*>(out_ys); }
        else {
            const int c = s - 1;
            src = cands + (size_t)c * LL;
            dst = reinterpret_cast<float4*>(out_ys) + (size_t)(1 + c) * VD4;
        }
    }
    if (active && j < LL) {
        int tok = src[j];
        toks[g][j] = tok;
        float w = freqs[tok];
        float sq = w * w;
        #pragma unroll
        for (int o = 16; o; o >>= 1) sq += __shfl_xor_sync(0xFFFFFFFFu, sq, o);
        ws[g][j] = w * rsqrtf(sq);
    }
    __syncthreads();
    if (active) {
        const float4* __restrict__ lt4 = reinterpret_cast<const float4*>(lt);
        float4 acc = make_float4(0.f, 0.f, 0.f, 0.f);
        #pragma unroll
        for (int l = 0; l < LL; l++) {
            const float w = ws[g][l];
            const float4 e = lt4[(size_t)toks[g][l] * VD4 + j];
            acc.x = fmaf(w, e.x, acc.x);
            acc.y = fmaf(w, e.y, acc.y);
            acc.z = fmaf(w, e.z, acc.z);
            acc.w = fmaf(w, e.w, acc.w);
        }
        __stcs(dst + j, acc);
    }
}

// ---------------------------------------------------------------------------
// Kernel 2: cosine of every mems_enc row vs row M (xs). (R8-identical.)
// ---------------------------------------------------------------------------
__global__ void cos_kernel()
{
    __shared__ float red[4][2][3];

    const int t = threadIdx.x;
    const int g = t >> 6;
    const int j = t & 63;
    const int r = blockIdx.x * 4 + g;
    if (r >= ROWS) return;

    const float4* __restrict__ enc4 = reinterpret_cast<const float4*>(g_mems_enc);
    const float4 mv = __ldcs(enc4 + (size_t)r * VD4 + j);
    const float4 xv = enc4[(size_t)MM * VD4 + j];

    float dot = mv.x * xv.x + mv.y * xv.y + mv.z * xv.z + mv.w * xv.w;
    float mn  = mv.x * mv.x + mv.y * mv.y + mv.z * mv.z + mv.w * mv.w;
    float xn  = xv.x * xv.x + xv.y * xv.y + xv.z * xv.z + xv.w * xv.w;

    #pragma unroll
    for (int o = 16; o; o >>= 1) {
        dot += __shfl_xor_sync(0xFFFFFFFFu, dot, o);
        mn  += __shfl_xor_sync(0xFFFFFFFFu, mn, o);
        xn  += __shfl_xor_sync(0xFFFFFFFFu, xn, o);
    }
    const int wig = j >> 5;
    if ((j & 31) == 0) {
        red[g][wig][0] = dot; red[g][wig][1] = mn; red[g][wig][2] = xn;
    }
    __syncthreads();

    if (j == 0) {
        float d  = red[g][0][0] + red[g][1][0];
        float m2 = red[g][0][1] + red[g][1][1];
        float x2 = red[g][0][2] + red[g][1][2];
        float an = fmaxf(sqrtf(x2), EPS);
        float bn = fmaxf(sqrtf(m2), EPS);
        g_cos[r] = d / (an * bn);
    }
}

// ---------------------------------------------------------------------------
// Kernel 3: fused softmax + partial att @ mems_enc. (R8-identical.)
// ---------------------------------------------------------------------------
__global__ void lhs_partial_kernel()
{
    __shared__ float  sred[8];
    __shared__ float4 scomb[4][VD4];

    const int t = threadIdx.x;
    const int lane = t & 31;
    const int wid  = t >> 5;

    float m = -INFINITY;
    for (int r = t; r < ROWS; r += 256) m = fmaxf(m, g_cos[r]);
    #pragma unroll
    for (int o = 16; o; o >>= 1) m = fmaxf(m, __shfl_xor_sync(0xFFFFFFFFu, m, o));
    if (lane == 0) sred[wid] = m;
    __syncthreads();
    {
        float mm = (t < 8) ? sred[t] : -INFINITY;
        if (wid == 0) {
            #pragma unroll
            for (int o = 4; o; o >>= 1) mm = fmaxf(mm, __shfl_xor_sync(0xFFFFFFFFu, mm, o));
            if (lane == 0) sred[0] = mm;
        }
    }
    __syncthreads();
    m = sred[0];
    __syncthreads();

    float s = 0.0f;
    for (int r = t; r < ROWS; r += 256) s += __expf(g_cos[r] - m);
    #pragma unroll
    for (int o = 16; o; o >>= 1) s += __shfl_xor_sync(0xFFFFFFFFu, s, o);
    if (lane == 0) sred[wid] = s;
    __syncthreads();
    {
        float ss = (t < 8) ? sred[t] : 0.0f;
        if (wid == 0) {
            #pragma unroll
            for (int o = 4; o; o >>= 1) ss += __shfl_xor_sync(0xFFFFFFFFu, ss, o);
            if (lane == 0) sred[0] = ss;
        }
    }
    __syncthreads();
    const float inv = 1.0f / sred[0];

    const int g = t >> 6;
    const int j = t & 63;
    const int base = (blockIdx.x * 4 + g) * 4;

    const float4* __restrict__ enc4 = reinterpret_cast<const float4*>(g_mems_enc);
    float4 acc = make_float4(0.f, 0.f, 0.f, 0.f);

    #pragma unroll
    for (int k = 0; k < 4; k++) {
        const int r = base + k;
        const float a = __expf(g_cos[r] - m) * inv;
        const float4 e = __ldcs(enc4 + (size_t)r * VD4 + j);
        acc.x = fmaf(a, e.x, acc.x);
        acc.y = fmaf(a, e.y, acc.y);
        acc.z = fmaf(a, e.z, acc.z);
        acc.w = fmaf(a, e.w, acc.w);
    }
    if (blockIdx.x == 0 && g == 0) {       // fold row 4096 (xs)
        const float a = __expf(g_cos[MM] - m) * inv;
        const float4 e = enc4[(size_t)MM * VD4 + j];
        acc.x = fmaf(a, e.x, acc.x);
        acc.y = fmaf(a, e.y, acc.y);
        acc.z = fmaf(a, e.z, acc.z);
        acc.w = fmaf(a, e.w, acc.w);
    }

    scomb[g][j] = acc;
    __syncthreads();

    if (g == 0) {
        float4 a0 = scomb[0][j], a1 = scomb[1][j], a2 = scomb[2][j], a3 = scomb[3][j];
        float4 r;
        r.x = (a0.x + a1.x) + (a2.x + a3.x);
        r.y = (a0.y + a1.y) + (a2.y + a3.y);
        r.z = (a0.z + a1.z) + (a2.z + a3.z);
        r.w = (a0.w + a1.w) + (a2.w + a3.w);
        reinterpret_cast<float4*>(g_partial)[(size_t)blockIdx.x * VD4 + j] = r;  // plain: keep L2
    }
}

// ---------------------------------------------------------------------------
// Kernel 4: reduce 256 partial rows -> g_lhs. 64 blocks. (R8-identical.)
// ---------------------------------------------------------------------------
__global__ void lhs_final_kernel()
{
    __shared__ float4 sred4[8];

    const int j = blockIdx.x;
    const int t = threadIdx.x;
    const int lane = t & 31;
    const int wid  = t >> 5;

    const float4* __restrict__ p4 = reinterpret_cast<const float4*>(g_partial);
    float4 v = p4[(size_t)t * VD4 + j];

    #pragma unroll
    for (int o = 16; o; o >>= 1) {
        v.x += __shfl_xor_sync(0xFFFFFFFFu, v.x, o);
        v.y += __shfl_xor_sync(0xFFFFFFFFu, v.y, o);
        v.z += __shfl_xor_sync(0xFFFFFFFFu, v.z, o);
        v.w += __shfl_xor_sync(0xFFFFFFFFu, v.w, o);
    }
    if (lane == 0) sred4[wid] = v;
    __syncthreads();

    if (t < 32) {
        float4 r = (lane < 8) ? sred4[lane] : make_float4(0.f, 0.f, 0.f, 0.f);
        #pragma unroll
        for (int o = 4; o; o >>= 1) {
            r.x += __shfl_xor_sync(0xFFFFFFFFu, r.x, o);
            r.y += __shfl_xor_sync(0xFFFFFFFFu, r.y, o);
            r.z += __shfl_xor_sync(0xFFFFFFFFu, r.z, o);
            r.w += __shfl_xor_sync(0xFFFFFFFFu, r.w, o);
        }
        if (lane == 0) reinterpret_cast<float4*>(g_lhs)[j] = r;
    }
}

// ---------------------------------------------------------------------------
// Kernel 5: tile g_lhs into xs_out. (R8-identical.)
// ---------------------------------------------------------------------------
__global__ void tile_kernel(float* __restrict__ out_xs)
{
    const int t = threadIdx.x;
    const int row = blockIdx.x * 4 + (t >> 6);
    const int j = t & 63;
    if (row <= CC) {
        const float4 v = reinterpret_cast<const float4*>(g_lhs)[j];
        __stcs(reinterpret_cast<float4*>(out_xs) + (size_t)row * VD4 + j, v);
    }
}

// ---------------------------------------------------------------------------
// Launch: during capture, rewrite the stream's capture dependencies so
// encode_out becomes an independent branch running concurrently with the
// cos -> lhs -> tile chain. CUDA 13 edge-data signatures. Falls back to a
// correct serial chain if anything declines.
// ---------------------------------------------------------------------------
extern "C" void kernel_launch(void* const* d_in, const int* in_sizes, int n_in,
                              void* d_out, int out_size)
{
    const int*   xs    = (const int*)  d_in[0];
    const int*   mems  = (const int*)  d_in[1];
    const int*   ys    = (const int*)  d_in[2];
    const int*   cands = (const int*)  d_in[3];
    const float* lt    = (const float*)d_in[4];
    const float* freqs = (const float*)d_in[5];

    float* out    = (float*)d_out;
    float* out_xs = out;                          // [C+1, D]
    float* out_ys = out + (size_t)(CC + 1) * VD;  // [C+1, D]

    const cudaStream_t st = 0;

    // K1: encode mems+xs
    encode_mems_kernel<<<1025, VD, 0, st>>>(xs, mems, lt, freqs);

    cudaStreamCaptureStatus cstat = cudaStreamCaptureStatusNone;
    cudaGraph_t cgraph = nullptr;
    const cudaGraphNode_t* deps = nullptr;
    const cudaGraphEdgeData* edges = nullptr;
    size_t ndeps = 0;
    bool surgery = false;
    cudaGraphNode_t n1 = nullptr;

    if (cudaStreamGetCaptureInfo(st, &cstat, nullptr, &cgraph, &deps, &edges, &ndeps)
            == cudaSuccess
        && cstat == cudaStreamCaptureStatusActive
        && ndeps == 1 && deps != nullptr) {
        n1 = deps[0];                                  // encode_mems node
        // Make the next launch a ROOT node (independent branch).
        if (cudaStreamUpdateCaptureDependencies(st, nullptr, nullptr, 0,
                cudaStreamSetCaptureDependencies) == cudaSuccess) {
            surgery = true;
        }
    }

    // K2: encode ys+cands (independent branch when surgery active)
    encode_out_kernel<<<1025, VD, 0, st>>>(ys, cands, lt, freqs, out_ys);

    cudaGraphNode_t n2 = nullptr;
    if (surgery) {
        // Record the encode_out node, then point the stream back at K1 so the
        // tail chain depends on encode_mems (not encode_out).
        if (cudaStreamGetCaptureInfo(st, &cstat, nullptr, &cgraph, &deps, &edges, &ndeps)
                == cudaSuccess && ndeps == 1 && deps != nullptr) {
            n2 = deps[0];
        }
        cudaGraphNode_t k1dep[1] = { n1 };
        if (n2 == nullptr ||
            cudaStreamUpdateCaptureDependencies(st, k1dep, nullptr, 1,
                cudaStreamSetCaptureDependencies) != cudaSuccess) {
            surgery = false;  // stays a serial chain (still correct: deps only tighten)
        }
    }

    // Tail chain (depends on encode_mems)
    cos_kernel<<<1025, VD, 0, st>>>();
    lhs_partial_kernel<<<NLHS, VD, 0, st>>>();
    lhs_final_kernel<<<VD4, VD, 0, st>>>();
    tile_kernel<<<1025, VD, 0, st>>>(out_xs);

    if (surgery && n2 != nullptr) {
        // Join: subsequent (harness) capture ops must depend on BOTH branches.
        if (cudaStreamGetCaptureInfo(st, &cstat, nullptr, &cgraph, &deps, &edges, &ndeps)
                == cudaSuccess && cstat == cudaStreamCaptureStatusActive
                && ndeps >= 1 && deps != nullptr) {
            cudaGraphNode_t fin[2] = { deps[0], n2 };  // tile node + encode_out node
            cudaStreamUpdateCaptureDependencies(st, fin, nullptr, 2,
                cudaStreamSetCaptureDependencies);
        }
    }
}

// round 17
// speedup vs baseline: 1.8002x; 1.1998x over previous
#include <cuda_runtime.h>
#include <math.h>

// Problem constants
#define VD    256
#define VD4   64
#define LL    32
#define MM    4096
#define CC    4096
#define ROWS  (MM + 1)     // mems_enc rows (mems + xs)
#define EPS   1e-8f
#define NLHS  256          // blocks for fused cos+partial stage

// Scratch (allocation-free: __device__ globals)
__device__ float g_mems_enc[ROWS * VD];
__device__ float g_partial[NLHS * VD];   // partial softmax numerators
__device__ float g_partial_s[NLHS];      // partial softmax denominators
__device__ float g_lhs[VD];

// ---------------------------------------------------------------------------
// Kernel 1a: encode mems + xs (4097 seqs, 1025 blocks x 256).
// ---------------------------------------------------------------------------
__global__ void encode_mems_kernel(const int* __restrict__ xs,
                                   const int* __restrict__ mems,
                                   const float* __restrict__ lt,
                                   const float* __restrict__ freqs)
{
    __shared__ int   toks[4][LL];
    __shared__ float ws[4][LL];

    const int t = threadIdx.x;
    const int g = t >> 6;
    const int j = t & 63;
    const int s = blockIdx.x * 4 + g;
    const bool active = (s < MM + 1);

    const int* src = mems;
    float4* dst = nullptr;
    if (active) {
        if (s < MM) {
            src = mems + (size_t)s * LL;
            dst = reinterpret_cast<float4*>(g_mems_enc) + (size_t)s * VD4;
        } else {
            src = xs;
            dst = reinterpret_cast<float4*>(g_mems_enc) + (size_t)MM * VD4;
        }
    }
    if (active && j < LL) {
        int tok = src[j];
        toks[g][j] = tok;
        float w = freqs[tok];
        float sq = w * w;
        #pragma unroll
        for (int o = 16; o; o >>= 1) sq += __shfl_xor_sync(0xFFFFFFFFu, sq, o);
        ws[g][j] = w * rsqrtf(sq);
    }
    __syncthreads();
    if (active) {
        const float4* __restrict__ lt4 = reinterpret_cast<const float4*>(lt);
        float4 acc = make_float4(0.f, 0.f, 0.f, 0.f);
        #pragma unroll
        for (int l = 0; l < LL; l++) {
            const float w = ws[g][l];
            const float4 e = lt4[(size_t)toks[g][l] * VD4 + j];
            acc.x = fmaf(w, e.x, acc.x);
            acc.y = fmaf(w, e.y, acc.y);
            acc.z = fmaf(w, e.z, acc.z);
            acc.w = fmaf(w, e.w, acc.w);
        }
        __stcs(dst + j, acc);        // streaming: keep lt L2-resident
    }
}

// ---------------------------------------------------------------------------
// Kernel 1b: encode ys + cands -> out_ys (independent graph branch).
// ---------------------------------------------------------------------------
__global__ void encode_out_kernel(const int* __restrict__ ys,
                                  const int* __restrict__ cands,
                                  const float* __restrict__ lt,
                                  const float* __restrict__ freqs,
                                  float* __restrict__ out_ys)
{
    __shared__ int   toks[4][LL];
    __shared__ float ws[4][LL];

    const int t = threadIdx.x;
    const int g = t >> 6;
    const int j = t & 63;
    const int s = blockIdx.x * 4 + g;
    const bool active = (s < MM + 1);      // ys + 4096 cands

    const int* src = cands;
    float4* dst = nullptr;
    if (active) {
        if (s == 0) { src = ys; dst = reinterpret_cast<float4*>(out_ys); }
        else {
            const int c = s - 1;
            src = cands + (size_t)c * LL;
            dst = reinterpret_cast<float4*>(out_ys) + (size_t)(1 + c) * VD4;
        }
    }
    if (active && j < LL) {
        int tok = src[j];
        toks[g][j] = tok;
        float w = freqs[tok];
        float sq = w * w;
        #pragma unroll
        for (int o = 16; o; o >>= 1) sq += __shfl_xor_sync(0xFFFFFFFFu, sq, o);
        ws[g][j] = w * rsqrtf(sq);
    }
    __syncthreads();
    if (active) {
        const float4* __restrict__ lt4 = reinterpret_cast<const float4*>(lt);
        float4 acc = make_float4(0.f, 0.f, 0.f, 0.f);
        #pragma unroll
        for (int l = 0; l < LL; l++) {
            const float w = ws[g][l];
            const float4 e = lt4[(size_t)toks[g][l] * VD4 + j];
            acc.x = fmaf(w, e.x, acc.x);
            acc.y = fmaf(w, e.y, acc.y);
            acc.z = fmaf(w, e.z, acc.z);
            acc.w = fmaf(w, e.w, acc.w);
        }
        __stcs(dst + j, acc);
    }
}

// ---------------------------------------------------------------------------
// Kernel 2: FUSED cos + softmax(shift=1) + partial weighted sum.
// 256 blocks x 256 threads; 64-thread group g handles rows base..base+3 in
// one register-resident pass (enc read ONCE). a_r = exp(cos_r - 1);
// partial N = sum a_r * enc_r (float4/thread), partial S = sum a_r.
// Block 0 / group 0 folds row 4096 (xs vs xs).
// ---------------------------------------------------------------------------
__global__ void cospartial_kernel()
{
    __shared__ float  red[4][4][2][2];   // [k][group][warp-in-group][{dot,mn}]
    __shared__ float  xred[4][2];        // [group][warp-in-group] xs norm^2
    __shared__ float4 scomb[4][VD4];
    __shared__ float  sa[4];

    const int t = threadIdx.x;
    const int g = t >> 6;
    const int j = t & 63;
    const int lane = t & 31;
    const int wig = j >> 5;

    const float4* __restrict__ enc4 = reinterpret_cast<const float4*>(g_mems_enc);
    const float4 xv = enc4[(size_t)MM * VD4 + j];    // hot xs row

    float xn = xv.x * xv.x + xv.y * xv.y + xv.z * xv.z + xv.w * xv.w;
    #pragma unroll
    for (int o = 16; o; o >>= 1) xn += __shfl_xor_sync(0xFFFFFFFFu, xn, o);
    if (lane == 0) xred[g][wig] = xn;

    const int base = (blockIdx.x * 4 + g) * 4;
    float4 mv[4];
    #pragma unroll
    for (int k = 0; k < 4; k++)
        mv[k] = __ldcs(enc4 + (size_t)(base + k) * VD4 + j);   // 4-deep MLP

    #pragma unroll
    for (int k = 0; k < 4; k++) {
        float dot = mv[k].x * xv.x + mv[k].y * xv.y + mv[k].z * xv.z + mv[k].w * xv.w;
        float mn  = mv[k].x * mv[k].x + mv[k].y * mv[k].y + mv[k].z * mv[k].z + mv[k].w * mv[k].w;
        #pragma unroll
        for (int o = 16; o; o >>= 1) {
            dot += __shfl_xor_sync(0xFFFFFFFFu, dot, o);
            mn  += __shfl_xor_sync(0xFFFFFFFFu, mn, o);
        }
        if (lane == 0) { red[k][g][wig][0] = dot; red[k][g][wig][1] = mn; }
    }
    __syncthreads();

    const float x2 = xred[g][0] + xred[g][1];
    const float an = fmaxf(sqrtf(x2), EPS);

    float4 acc = make_float4(0.f, 0.f, 0.f, 0.f);
    float s_loc = 0.0f;
    #pragma unroll
    for (int k = 0; k < 4; k++) {
        const float d  = red[k][g][0][0] + red[k][g][1][0];
        const float m2 = red[k][g][0][1] + red[k][g][1][1];
        const float bn = fmaxf(sqrtf(m2), EPS);
        const float a  = __expf(d / (an * bn) - 1.0f);
        acc.x = fmaf(a, mv[k].x, acc.x);
        acc.y = fmaf(a, mv[k].y, acc.y);
        acc.z = fmaf(a, mv[k].z, acc.z);
        acc.w = fmaf(a, mv[k].w, acc.w);
        s_loc += a;
    }
    if (blockIdx.x == 0 && g == 0) {                 // fold row 4096 (xs)
        const float a = __expf(x2 / (an * an) - 1.0f);
        acc.x = fmaf(a, xv.x, acc.x);
        acc.y = fmaf(a, xv.y, acc.y);
        acc.z = fmaf(a, xv.z, acc.z);
        acc.w = fmaf(a, xv.w, acc.w);
        s_loc += a;
    }

    scomb[g][j] = acc;
    if (j == 0) sa[g] = s_loc;
    __syncthreads();

    if (g == 0) {
        float4 a0 = scomb[0][j], a1 = scomb[1][j], a2 = scomb[2][j], a3 = scomb[3][j];
        float4 r;
        r.x = (a0.x + a1.x) + (a2.x + a3.x);
        r.y = (a0.y + a1.y) + (a2.y + a3.y);
        r.z = (a0.z + a1.z) + (a2.z + a3.z);
        r.w = (a0.w + a1.w) + (a2.w + a3.w);
        reinterpret_cast<float4*>(g_partial)[(size_t)blockIdx.x * VD4 + j] = r;  // plain: keep L2
        if (t == 0) g_partial_s[blockIdx.x] = (sa[0] + sa[1]) + (sa[2] + sa[3]);
    }
}

// ---------------------------------------------------------------------------
// Kernel 3: reduce 256 partial (N, S) -> g_lhs = N_total / S_total.
// 64 blocks (one per float4 column) x 256 threads.
// ---------------------------------------------------------------------------
__global__ void lhs_final_kernel()
{
    __shared__ float4 sred4[8];
    __shared__ float  ssum[8];

    const int col = blockIdx.x;
    const int t = threadIdx.x;
    const int lane = t & 31;
    const int wid  = t >> 5;

    const float4* __restrict__ p4 = reinterpret_cast<const float4*>(g_partial);
    float4 v = p4[(size_t)t * VD4 + col];
    float  s = g_partial_s[t];

    #pragma unroll
    for (int o = 16; o; o >>= 1) {
        v.x += __shfl_xor_sync(0xFFFFFFFFu, v.x, o);
        v.y += __shfl_xor_sync(0xFFFFFFFFu, v.y, o);
        v.z += __shfl_xor_sync(0xFFFFFFFFu, v.z, o);
        v.w += __shfl_xor_sync(0xFFFFFFFFu, v.w, o);
        s   += __shfl_xor_sync(0xFFFFFFFFu, s, o);
    }
    if (lane == 0) { sred4[wid] = v; ssum[wid] = s; }
    __syncthreads();

    if (t < 32) {
        float4 r = (lane < 8) ? sred4[lane] : make_float4(0.f, 0.f, 0.f, 0.f);
        float  st = (lane < 8) ? ssum[lane] : 0.0f;
        #pragma unroll
        for (int o = 4; o; o >>= 1) {
            r.x += __shfl_xor_sync(0xFFFFFFFFu, r.x, o);
            r.y += __shfl_xor_sync(0xFFFFFFFFu, r.y, o);
            r.z += __shfl_xor_sync(0xFFFFFFFFu, r.z, o);
            r.w += __shfl_xor_sync(0xFFFFFFFFu, r.w, o);
            st  += __shfl_xor_sync(0xFFFFFFFFu, st, o);
        }
        if (lane == 0) {
            const float inv = 1.0f / st;
            reinterpret_cast<float4*>(g_lhs)[col] =
                make_float4(r.x * inv, r.y * inv, r.z * inv, r.w * inv);
        }
    }
}

// ---------------------------------------------------------------------------
// Kernel 4: tile g_lhs into xs_out. (R8-identical.)
// ---------------------------------------------------------------------------
__global__ void tile_kernel(float* __restrict__ out_xs)
{
    const int t = threadIdx.x;
    const int row = blockIdx.x * 4 + (t >> 6);
    const int j = t & 63;
    if (row <= CC) {
        const float4 v = reinterpret_cast<const float4*>(g_lhs)[j];
        __stcs(reinterpret_cast<float4*>(out_xs) + (size_t)row * VD4 + j, v);
    }
}

// ---------------------------------------------------------------------------
// Launch with capture-graph surgery (CUDA 13 edge-data signatures):
// encode_out runs as an independent branch concurrent with the tail chain.
// ---------------------------------------------------------------------------
extern "C" void kernel_launch(void* const* d_in, const int* in_sizes, int n_in,
                              void* d_out, int out_size)
{
    const int*   xs    = (const int*)  d_in[0];
    const int*   mems  = (const int*)  d_in[1];
    const int*   ys    = (const int*)  d_in[2];
    const int*   cands = (const int*)  d_in[3];
    const float* lt    = (const float*)d_in[4];
    const float* freqs = (const float*)d_in[5];

    float* out    = (float*)d_out;
    float* out_xs = out;                          // [C+1, D]
    float* out_ys = out + (size_t)(CC + 1) * VD;  // [C+1, D]

    const cudaStream_t st = 0;

    // K1: encode mems+xs
    encode_mems_kernel<<<1025, VD, 0, st>>>(xs, mems, lt, freqs);

    cudaStreamCaptureStatus cstat = cudaStreamCaptureStatusNone;
    cudaGraph_t cgraph = nullptr;
    const cudaGraphNode_t* deps = nullptr;
    const cudaGraphEdgeData* edges = nullptr;
    size_t ndeps = 0;
    bool surgery = false;
    cudaGraphNode_t n1 = nullptr;

    if (cudaStreamGetCaptureInfo(st, &cstat, nullptr, &cgraph, &deps, &edges, &ndeps)
            == cudaSuccess
        && cstat == cudaStreamCaptureStatusActive
        && ndeps == 1 && deps != nullptr) {
        n1 = deps[0];                                  // encode_mems node
        if (cudaStreamUpdateCaptureDependencies(st, nullptr, nullptr, 0,
                cudaStreamSetCaptureDependencies) == cudaSuccess) {
            surgery = true;
        }
    }

    // K2: encode ys+cands (independent branch when surgery active)
    encode_out_kernel<<<1025, VD, 0, st>>>(ys, cands, lt, freqs, out_ys);

    cudaGraphNode_t n2 = nullptr;
    if (surgery) {
        if (cudaStreamGetCaptureInfo(st, &cstat, nullptr, &cgraph, &deps, &edges, &ndeps)
                == cudaSuccess && ndeps == 1 && deps != nullptr) {
            n2 = deps[0];
        }
        cudaGraphNode_t k1dep[1] = { n1 };
        if (n2 == nullptr ||
            cudaStreamUpdateCaptureDependencies(st, k1dep, nullptr, 1,
                cudaStreamSetCaptureDependencies) != cudaSuccess) {
            surgery = false;
        }
    }

    // Tail chain (depends on encode_mems)
    cospartial_kernel<<<NLHS, VD, 0, st>>>();
    lhs_final_kernel<<<VD4, VD, 0, st>>>();
    tile_kernel<<<1025, VD, 0, st>>>(out_xs);

    if (surgery && n2 != nullptr) {
        if (cudaStreamGetCaptureInfo(st, &cstat, nullptr, &cgraph, &deps, &edges, &ndeps)
                == cudaSuccess && cstat == cudaStreamCaptureStatusActive
                && ndeps >= 1 && deps != nullptr) {
            cudaGraphNode_t fin[2] = { deps[0], n2 };  // tile node + encode_out node
            cudaStreamUpdateCaptureDependencies(st, fin, nullptr, 2,
                cudaStreamSetCaptureDependencies);
        }
    }
}